// round 4
// baseline (speedup 1.0000x reference)
#include <cuda_runtime.h>

// 9x9 zero-padded box filter, 128 independent 512x512 fp32 images.
// Warp-autonomous: each warp owns a full-width 512 x RB row band.
// No shared memory, no barriers. Column mapping is interleaved:
// lane t, group g owns float4 column index g*32+t, so every global
// access is a perfectly coalesced 512B warp transaction. Horizontal
// halos come from neighbor lanes via shfl with a source-side register
// select at the warp seams.

#define W   512
#define H   512
#define W4  128                 // float4 columns per row
#define RB  16                  // rows per warp band
#define WPB 4                   // warps per block

__global__ __launch_bounds__(WPB * 32)
void box9_kernel(const float* __restrict__ xin, float* __restrict__ outp) {
    const int lane = threadIdx.x & 31;
    const int wid  = threadIdx.x >> 5;
    const int y0   = (blockIdx.x * WPB + wid) * RB;
    const size_t imgoff = (size_t)blockIdx.y * (W * H);
    const float4* __restrict__ base  = reinterpret_cast<const float4*>(xin + imgoff);
    float4* __restrict__       obase = reinterpret_cast<float4*>(outp + imgoff);

    const float4 z4 = make_float4(0.f, 0.f, 0.f, 0.f);
    float4 vs[4];
    #pragma unroll
    for (int g = 0; g < 4; g++) vs[g] = z4;

    // ---- prologue: vs = sum of input rows [y0-5, y0+3] (zeros outside) ----
    // Invariant before the slide at output row y: vs = sum rows [y-5, y+3].
    #pragma unroll
    for (int i = -5; i <= 3; i++) {
        int r = y0 + i;
        if ((unsigned)r < (unsigned)H) {
            #pragma unroll
            for (int g = 0; g < 4; g++) {
                float4 v = base[r * W4 + g * 32 + lane];
                vs[g].x += v.x; vs[g].y += v.y; vs[g].z += v.z; vs[g].w += v.w;
            }
        }
    }

    #pragma unroll 2
    for (int k = 0; k < RB; k++) {
        const int y  = y0 + k;
        const int rn = y + 4;     // always >= 4
        const int ro = y - 5;     // always < H

        // batch all loads up front for MLP
        float4 nv[4], ov[4];
        #pragma unroll
        for (int g = 0; g < 4; g++) {
            nv[g] = (rn < H) ? base[rn * W4 + g * 32 + lane] : z4;
            ov[g] = (ro >= 0) ? base[ro * W4 + g * 32 + lane] : z4;
        }

        // vertical slide
        #pragma unroll
        for (int g = 0; g < 4; g++) {
            vs[g].x += nv[g].x - ov[g].x;
            vs[g].y += nv[g].y - ov[g].y;
            vs[g].z += nv[g].z - ov[g].z;
            vs[g].w += nv[g].w - ov[g].w;
        }

        // horizontal 9-sum per group via lane shuffles
        #pragma unroll
        for (int g = 0; g < 4; g++) {
            const int gm = (g == 0) ? 0 : g - 1;   // dummy for g==0 (zeroed below)
            const int gp = (g == 3) ? 3 : g + 1;   // dummy for g==3 (zeroed below)

            // left halo: float4 column index g*32+lane-1
            float4 vsl = (lane == 31) ? vs[gm] : vs[g];
            float4 L;
            L.x = __shfl_sync(0xffffffffu, vsl.x, (lane + 31) & 31);
            L.y = __shfl_sync(0xffffffffu, vsl.y, (lane + 31) & 31);
            L.z = __shfl_sync(0xffffffffu, vsl.z, (lane + 31) & 31);
            L.w = __shfl_sync(0xffffffffu, vsl.w, (lane + 31) & 31);
            if (g == 0 && lane == 0) L = z4;       // image left edge

            // right halo: float4 column index g*32+lane+1
            float4 vsr = (lane == 0) ? vs[gp] : vs[g];
            float4 R;
            R.x = __shfl_sync(0xffffffffu, vsr.x, (lane + 1) & 31);
            R.y = __shfl_sync(0xffffffffu, vsr.y, (lane + 1) & 31);
            R.z = __shfl_sync(0xffffffffu, vsr.z, (lane + 1) & 31);
            R.w = __shfl_sync(0xffffffffu, vsr.w, (lane + 1) & 31);
            if (g == 3 && lane == 31) R = z4;      // image right edge

            float4 V = vs[g];
            float o0 = ((L.x + L.y) + (L.z + L.w))
                     + ((V.x + V.y) + (V.z + V.w)) + R.x;
            float o1 = o0 - L.x + R.y;
            float o2 = o1 - L.y + R.z;
            float o3 = o2 - L.z + R.w;
            obase[y * W4 + g * 32 + lane] = make_float4(o0, o1, o2, o3);
        }
    }
}

extern "C" void kernel_launch(void* const* d_in, const int* in_sizes, int n_in,
                              void* d_out, int out_size) {
    const float* x = (const float*)d_in[0];
    float* out = (float*)d_out;
    int nimg = in_sizes[0] / (W * H);                 // 128
    dim3 grid((H / RB) / WPB, nimg);                  // (8, 128) = 1024 CTAs
    box9_kernel<<<grid, WPB * 32>>>(x, out);
}

// round 5
// speedup vs baseline: 1.6812x; 1.6812x over previous
#include <cuda_runtime.h>

// 9x9 zero-padded box filter, 128 independent 512x512 fp32 images.
// Full-width row pipeline (R3 structure): CTA = 512-wide x TH-row band.
// Vertical 9-sum slides in registers (new row from DRAM, old row from L1/L2),
// horizontal 9-sum via one smem float4 store + 2 neighbor float4 loads.
// R5: TH=32 (2x CTAs -> ~80% occupancy) and 4 rows per barrier (8-slot ring).

#define W   512
#define H   512
#define TH  32                  // rows per CTA band
#define NT  128                 // one thread per float4 column group (512/4)
#define W4  (W / 4)             // 128
#define SLW 130                 // smem slot width in float4 (128 + 2 halo)

__global__ __launch_bounds__(NT) void box9_kernel(const float* __restrict__ xin,
                                                  float* __restrict__ outp) {
    // 8 row-slots: 4 rows in flight per barrier, double-buffered halves.
    // Slot s holds vsum row; index t+1 is own column, 0 and 129 are zero halo.
    __shared__ __align__(16) float4 buf[8][SLW];

    const int t  = threadIdx.x;
    const int y0 = blockIdx.x * TH;
    const size_t imgoff = (size_t)blockIdx.y * (W * H);
    const float4* __restrict__ base  = reinterpret_cast<const float4*>(xin + imgoff);
    float4* __restrict__       obase = reinterpret_cast<float4*>(outp + imgoff);

    const float4 z4 = make_float4(0.f, 0.f, 0.f, 0.f);
    if (t < 8) {
        buf[t][0]       = z4;
        buf[t][SLW - 1] = z4;
    }

    // ---- prologue: vs = sum of input rows [y0-5, y0+3] (zeros outside) ----
    // Invariant before the slide at output row y: vs = sum rows [y-5, y+3].
    float4 vs = z4;
    #pragma unroll
    for (int i = -5; i <= 3; i++) {
        int r = y0 + i;
        if ((unsigned)r < (unsigned)H) {
            float4 v = base[r * W4 + t];
            vs.x += v.x; vs.y += v.y; vs.z += v.z; vs.w += v.w;
        }
    }

    // prefetch rows for the first group (output rows y0..y0+3):
    //   n[i] = x[y0+i+4], o[i] = x[y0+i-5]
    float4 pn[4], po[4];
    #pragma unroll
    for (int i = 0; i < 4; i++) {
        int rn = y0 + i + 4, ro = y0 + i - 5;
        pn[i] = ((unsigned)rn < (unsigned)H) ? base[rn * W4 + t] : z4;
        po[i] = ((unsigned)ro < (unsigned)H) ? base[ro * W4 + t] : z4;
    }

    #pragma unroll 2
    for (int k = 0; k < TH / 4; k++) {
        const int y = y0 + 4 * k;
        float4 n[4], o[4];
        #pragma unroll
        for (int i = 0; i < 4; i++) { n[i] = pn[i]; o[i] = po[i]; }

        // prefetch rows for next group (output rows y+4..y+7)
        if (k + 1 < TH / 4) {
            #pragma unroll
            for (int i = 0; i < 4; i++) {
                int rn = y + i + 8, ro = y + i - 1;
                pn[i] = ((unsigned)rn < (unsigned)H) ? base[rn * W4 + t] : z4;
                po[i] = ((unsigned)ro < (unsigned)H) ? base[ro * W4 + t] : z4;
            }
        }

        // vertical slide, 4 rows; stash vsums in the smem ring
        float4 vsr[4];
        #pragma unroll
        for (int i = 0; i < 4; i++) {
            vs.x += n[i].x - o[i].x;
            vs.y += n[i].y - o[i].y;
            vs.z += n[i].z - o[i].z;
            vs.w += n[i].w - o[i].w;
            vsr[i] = vs;
            buf[(4 * k + i) & 7][t + 1] = vs;
        }

        __syncthreads();

        // horizontal slide, 4 rows
        #pragma unroll
        for (int i = 0; i < 4; i++) {
            float4 a = buf[(4 * k + i) & 7][t];
            float4 c = buf[(4 * k + i) & 7][t + 2];
            float4 V = vsr[i];
            float sb = (V.x + V.y) + (V.z + V.w);
            float sa = (a.x + a.y) + (a.z + a.w);
            float h0 = sa + sb + c.x;
            float h1 = h0 - a.x + c.y;
            float h2 = h1 - a.y + c.z;
            float h3 = h2 - a.z + c.w;
            obase[(y + i) * W4 + t] = make_float4(h0, h1, h2, h3);
        }
    }
}

extern "C" void kernel_launch(void* const* d_in, const int* in_sizes, int n_in,
                              void* d_out, int out_size) {
    const float* x = (const float*)d_in[0];
    float* out = (float*)d_out;
    int nimg = in_sizes[0] / (W * H);     // 128
    dim3 grid(H / TH, nimg);              // (16, 128) = 2048 CTAs
    box9_kernel<<<grid, NT>>>(x, out);
}